// round 1
// baseline (speedup 1.0000x reference)
#include <cuda_runtime.h>

#define B 32
#define M 32
#define C 1024
#define R 28
#define INV_R2 (1.0f / (R * R))

// Scratch (allocation-free rule: __device__ globals)
__device__ float g_row[B * C * R];   // row sums of F_feat: (B, C, R)
__device__ float g_col[B * M * R];   // column sums of Masks: (B, M, R)

// ---------------------------------------------------------------------------
// Kernel 1: row[b,c,i] = sum_j F[b,c,i,j]
// One thread per (b,c,i) row of 28 contiguous floats = 7 float4 loads.
// 112 bytes per row, 16B-aligned (112 = 7*16). Warp covers a contiguous
// 3584B span; all lines fully consumed. MLP = 7 per thread via full unroll.
// ---------------------------------------------------------------------------
__global__ void reduce_F_kernel(const float* __restrict__ F) {
    int tid = blockIdx.x * blockDim.x + threadIdx.x;
    if (tid >= B * C * R) return;
    const float4* p = reinterpret_cast<const float4*>(F + (size_t)tid * R);
    float4 v0 = p[0], v1 = p[1], v2 = p[2], v3 = p[3];
    float4 v4 = p[4], v5 = p[5], v6 = p[6];
    float s = (v0.x + v0.y) + (v0.z + v0.w)
            + (v1.x + v1.y) + (v1.z + v1.w)
            + (v2.x + v2.y) + (v2.z + v2.w)
            + (v3.x + v3.y) + (v3.z + v3.w)
            + (v4.x + v4.y) + (v4.z + v4.w)
            + (v5.x + v5.y) + (v5.z + v5.w)
            + (v6.x + v6.y) + (v6.z + v6.w);
    g_row[tid] = s;
}

// ---------------------------------------------------------------------------
// Kernel 2: col[b,m,j] = sum_i Masks[b,m,i,j]
// One thread per (b,m,j); loop over i with stride R. Adjacent threads ->
// adjacent j -> coalesced per iteration. Only 3.2 MB total.
// ---------------------------------------------------------------------------
__global__ void reduce_M_kernel(const float* __restrict__ Mk) {
    int tid = blockIdx.x * blockDim.x + threadIdx.x;
    if (tid >= B * M * R) return;
    int j  = tid % R;
    int bm = tid / R;
    const float* p = Mk + (size_t)bm * R * R + j;
    float s = 0.0f;
#pragma unroll
    for (int i = 0; i < R; i++) s += p[i * R];
    g_col[tid] = s;
}

// ---------------------------------------------------------------------------
// Kernel 3: S[b,m,c] = (1/784) * sum_r col[b,m,r] * row[b,c,r]
// Grid (B, C/128), block 128. col_b staged in smem (broadcast reads),
// row[b,c,:] in 28 registers per thread. Stores coalesced over c.
// ---------------------------------------------------------------------------
__global__ void einsum_kernel(float* __restrict__ out) {
    __shared__ float col_s[M * R];  // 896 floats
    const int b = blockIdx.x;
    const int c = blockIdx.y * blockDim.x + threadIdx.x;

    for (int i = threadIdx.x; i < M * R; i += blockDim.x)
        col_s[i] = g_col[b * M * R + i];
    __syncthreads();

    float rowv[R];
    const float* rp = g_row + ((size_t)b * C + c) * R;
#pragma unroll
    for (int r = 0; r < R; r++) rowv[r] = rp[r];

#pragma unroll 4
    for (int m = 0; m < M; m++) {
        float acc = 0.0f;
#pragma unroll
        for (int r = 0; r < R; r++) acc += col_s[m * R + r] * rowv[r];
        out[((size_t)b * M + m) * C + c] = acc * INV_R2;
    }
}

extern "C" void kernel_launch(void* const* d_in, const int* in_sizes, int n_in,
                              void* d_out, int out_size) {
    const float* F  = (const float*)d_in[0];  // (B, C, R, R)
    const float* Mk = (const float*)d_in[1];  // (B, M, R, R)
    float* out = (float*)d_out;               // (B, M, C)

    {
        int n = B * C * R;
        reduce_F_kernel<<<(n + 255) / 256, 256>>>(F);
    }
    {
        int n = B * M * R;
        reduce_M_kernel<<<(n + 255) / 256, 256>>>(Mk);
    }
    {
        dim3 grid(B, C / 128);
        einsum_kernel<<<grid, 128>>>(out);
    }
}